// round 15
// baseline (speedup 1.0000x reference)
#include <cuda_runtime.h>
#include <cuda_fp16.h>
#include <cstdint>
#include <math.h>

// ---------------- problem constants ----------------
#define NB 32
#define C_EMB 128
#define HID 32
#define KIDX 100

#define HW_0 6400
#define HW_1 1600
#define HW_2 400
#define SIDE0 80
#define SIDE1 40
#define SIDE2 20

#define NBHW0 (NB * HW_0)
#define NBHW1 (NB * HW_1)
#define NBHW2 (NB * HW_2)

#define NW0 (C_EMB * 256)
#define NW1 (C_EMB * 512)
#define NW2 (C_EMB * 1024)

// ---------------- device scratch ----------------
__device__ __align__(128) __half g_y0s0[(size_t)NBHW0 * C_EMB];
__device__ __align__(128) __half g_y0s1[(size_t)NBHW1 * C_EMB];
__device__ __align__(128) __half g_y0s2[(size_t)NBHW2 * C_EMB];

__device__ __align__(128) __half g_wh0[NW0];
__device__ __align__(128) __half g_wh1[NW1];
__device__ __align__(128) __half g_wh2[NW2];

__device__ unsigned g_maxenc[3 * NB * C_EMB];
__device__ float    g_sum[3 * NB * C_EMB];
__device__ float    g_gate[3 * NB * C_EMB];
__device__ unsigned g_gateh[3 * NB * (C_EMB / 2)];

// ---------------- helpers ----------------
__device__ __forceinline__ uint32_t smem_to_u32(const void* p) {
    uint32_t a;
    asm("{ .reg .u64 t; cvta.to.shared.u64 t, %1; cvt.u32.u64 %0, t; }" : "=r"(a) : "l"(p));
    return a;
}
__device__ __forceinline__ void ldsm_x4(uint32_t* r, uint32_t addr) {
    asm volatile("ldmatrix.sync.aligned.m8n8.x4.shared.b16 {%0,%1,%2,%3}, [%4];"
                 : "=r"(r[0]), "=r"(r[1]), "=r"(r[2]), "=r"(r[3]) : "r"(addr));
}
__device__ __forceinline__ void ldsm_x4_t(uint32_t* r, uint32_t addr) {
    asm volatile("ldmatrix.sync.aligned.m8n8.x4.trans.shared.b16 {%0,%1,%2,%3}, [%4];"
                 : "=r"(r[0]), "=r"(r[1]), "=r"(r[2]), "=r"(r[3]) : "r"(addr));
}
__device__ __forceinline__ void mma_f16(float* d, const uint32_t* a, const uint32_t* b) {
    asm volatile("mma.sync.aligned.m16n8k16.row.col.f32.f16.f16.f32 "
                 "{%0,%1,%2,%3}, {%4,%5,%6,%7}, {%8,%9}, {%0,%1,%2,%3};"
                 : "+f"(d[0]), "+f"(d[1]), "+f"(d[2]), "+f"(d[3])
                 : "r"(a[0]), "r"(a[1]), "r"(a[2]), "r"(a[3]), "r"(b[0]), "r"(b[1]));
}
__device__ __forceinline__ void cp_async16(uint32_t saddr, const void* gptr) {
    asm volatile("cp.async.cg.shared.global [%0], [%1], 16;" :: "r"(saddr), "l"(gptr));
}
#define CP_COMMIT() asm volatile("cp.async.commit_group;" ::: "memory")
#define CP_WAIT0()  asm volatile("cp.async.wait_group 0;"  ::: "memory")

__device__ __forceinline__ unsigned encf(float f) {
    unsigned u = __float_as_uint(f);
    return (u & 0x80000000u) ? ~u : (u | 0x80000000u);
}
__device__ __forceinline__ float decf(unsigned e) {
    return (e & 0x80000000u) ? __uint_as_float(e & 0x7FFFFFFFu) : __uint_as_float(~e);
}
__device__ __forceinline__ float sigmoidf_(float x) { return 1.0f / (1.0f + __expf(-x)); }

// ---------------- setup ----------------
__global__ void setup_all(const float* __restrict__ nw0, const float* __restrict__ nw1,
                          const float* __restrict__ nw2) {
    int i = blockIdx.x * 256 + threadIdx.x;
    if (i < 3 * NB * C_EMB) { g_maxenc[i] = 0u; g_sum[i] = 0.0f; }
    if (i < NW0)                  g_wh0[i] = __float2half_rn(nw0[i]);
    else if (i < NW0 + NW1)       g_wh1[i - NW0] = __float2half_rn(nw1[i - NW0]);
    else if (i < NW0 + NW1 + NW2) g_wh2[i - NW0 - NW1] = __float2half_rn(nw2[i - NW0 - NW1]);
}

// ---------------- merged HMMA GEMM: 64hw x 128ch, 3 CTAs/SM, 2-tile scale0 ----------------
// smem: X fp16 2 x 8 KB at 0; W fp16 2 x 16 KB at 16384; bias at 49152; red at 49664.
// Buffer parity starts at 1 so the tile-final chunk uses buf0; the epilogue's Cs
// staging (17408 B from offset 0) clobbers X bufs + first KB of W buf0 only, so
// the next tile's W chunk0 prefetch into W buf1 survives the epilogue.
static constexpr int SM_XB0  = 0;
static constexpr int SM_WB0  = 16384;
static constexpr int SM_BIAS = 49152;
static constexpr int SM_RED  = 49664;
static constexpr int SMEM_GEMM = 49664 + 2048;
static constexpr int CS_STRIDE = 136;

__global__ void __launch_bounds__(256, 3)
gemm_all(const float* __restrict__ x0, const float* __restrict__ x1, const float* __restrict__ x2,
         const __half* __restrict__ wh0, const __half* __restrict__ wh1, const __half* __restrict__ wh2,
         const float* __restrict__ nb0, const float* __restrict__ nb1, const float* __restrict__ nb2,
         __half* __restrict__ y0, __half* __restrict__ y1, __half* __restrict__ y2) {
    extern __shared__ __align__(128) char smem[];
    const uint32_t sb = smem_to_u32(smem);
    const int tid  = threadIdx.x;
    const int lane = tid & 31;
    const int wid  = tid >> 5;
    const int wm   = wid & 1;
    const int wn   = wid >> 1;
    const int b    = blockIdx.y;

    const float* X; const __half* Wh; const float* bias; __half* Y;
    int CIN, HW, scale, tile0, ntiles;
    int bx = blockIdx.x;
    if (bx < 7)       { scale = 2; tile0 = bx;            ntiles = 1; X = x2; Wh = wh2; bias = nb2; Y = y2; CIN = 1024; HW = HW_2; }
    else if (bx < 32) { scale = 1; tile0 = bx - 7;        ntiles = 1; X = x1; Wh = wh1; bias = nb1; Y = y1; CIN = 512;  HW = HW_1; }
    else              { scale = 0; tile0 = (bx - 32) * 2; ntiles = 2; X = x0; Wh = wh0; bias = nb0; Y = y0; CIN = 256;  HW = HW_0; }
    const int nchunk = CIN >> 6;
    int hw0 = tile0 * 64;

    if (tid < 32) ((float4*)(smem + SM_BIAS))[tid] = ((const float4*)bias)[tid];

    const int ti = lane & 7;
    const int gq = lane >> 3;
    const int aKrow = ((gq >> 1) << 3) + ti;
    const int aMsel = (gq & 1) << 3;
    const int bKsel = gq & 1;
    const int bNrow = ((gq >> 1) << 3) + ti;

    uint32_t offA[2];
#pragma unroll
    for (int mt = 0; mt < 2; mt++) {
        int m0 = wm * 32 + mt * 16 + aMsel;
        offA[mt] = (uint32_t)(aKrow * 128 + ((((m0 >> 3) ^ (aKrow & 7)) << 4)));
    }

    const int xr  = tid >> 2;
    const int xc0 = tid & 3;
    const float* xb_b = X + (size_t)b * CIN * HW;

    uint2 xpA[4], xpB[4];

#define LDG_XT(HWB, K0, SET) do { \
        const float* row_ = xb_b + (size_t)((K0) + xr) * HW + (HWB); \
        _Pragma("unroll") \
        for (int i_ = 0; i_ < 4; i_++) { \
            int c4_ = xc0 + 4 * i_; \
            int hwb_ = c4_ * 4; \
            float4 v_ = ((HWB) + hwb_ < HW) ? *(const float4*)(row_ + hwb_) \
                                            : make_float4(0.f, 0.f, 0.f, 0.f); \
            __half2 p0_ = __floats2half2_rn(v_.x, v_.y); \
            __half2 p1_ = __floats2half2_rn(v_.z, v_.w); \
            (SET)[i_] = make_uint2(*(uint32_t*)&p0_, *(uint32_t*)&p1_); \
        } \
    } while (0)

#define STS_X(SET, BUF) do { \
        uint32_t base_ = sb + SM_XB0 + (BUF) * 8192; \
        _Pragma("unroll") \
        for (int i_ = 0; i_ < 4; i_++) { \
            int c4_ = xc0 + 4 * i_; \
            uint32_t off_ = (uint32_t)(xr * 128 + ((((c4_ >> 1) ^ (xr & 7)) << 4)) + (c4_ & 1) * 8); \
            asm volatile("st.shared.v2.b32 [%0], {%1, %2};" :: "r"(base_ + off_), "r"((SET)[i_].x), "r"((SET)[i_].y)); \
        } \
    } while (0)

#define CPA_W(K0, BUF) do { \
        uint32_t wb_ = sb + SM_WB0 + (BUF) * 16384; \
        _Pragma("unroll") \
        for (int i_ = 0; i_ < 4; i_++) { \
            int idx_ = tid + i_ * 256; \
            int n_   = idx_ >> 3; \
            int seg_ = idx_ & 7; \
            uint32_t off_ = (uint32_t)(n_ * 128 + ((seg_ ^ (n_ & 7)) << 4)); \
            cp_async16(wb_ + off_, Wh + (size_t)n_ * CIN + (K0) + seg_ * 8); \
        } \
    } while (0)

    // ---- prologue (tile 0): everything starts in buffer 1 ----
    CPA_W(0, 1);
    CP_COMMIT();
    LDG_XT(hw0, 0, xpA);
    STS_X(xpA, 1);
    LDG_XT(hw0, 64, xpB);
    CP_WAIT0();
    __syncthreads();

    for (int t = 0; ; t++) {
        float acc[2][4][4];
#pragma unroll
        for (int mt = 0; mt < 2; mt++)
#pragma unroll
            for (int nt = 0; nt < 4; nt++)
#pragma unroll
                for (int r = 0; r < 4; r++) acc[mt][nt][r] = 0.0f;

        int nvalid = HW - hw0; if (nvalid > 64) nvalid = 64;

        for (int ck = 0; ck < nchunk; ck++) {
            const int buf = 1 ^ (ck & 1);
            const int nxt = buf ^ 1;
            if (ck + 1 < nchunk) {
                if ((ck + 1) & 1) STS_X(xpB, nxt); else STS_X(xpA, nxt);
                CPA_W((ck + 1) * 64, nxt);
                CP_COMMIT();
            } else if (t + 1 < ntiles) {
                CPA_W(0, nxt);          // nxt==1 (high buffer, survives epilogue)
                CP_COMMIT();
            }
            if (ck + 2 < nchunk) {
                if (ck & 1) LDG_XT(hw0, (ck + 2) * 64, xpB);
                else        LDG_XT(hw0, (ck + 2) * 64, xpA);
            } else if (t + 1 < ntiles) {
                const int kn = (ck + 2 - nchunk) * 64;   // 0 then 64
                if (ck & 1) LDG_XT(hw0 + 64, kn, xpB);
                else        LDG_XT(hw0 + 64, kn, xpA);
            }
            const uint32_t xb = sb + SM_XB0 + buf * 8192;
            const uint32_t wb = sb + SM_WB0 + buf * 16384;
#pragma unroll
            for (int ks = 0; ks < 4; ks++) {
                const uint32_t kb = (uint32_t)(ks * 16 * 128);
                uint32_t ah[2][4];
                ldsm_x4_t(ah[0], xb + kb + offA[0]);
                ldsm_x4_t(ah[1], xb + kb + offA[1]);
#pragma unroll
                for (int np = 0; np < 2; np++) {
                    int nrow = wn * 32 + np * 16 + bNrow;
                    int kseg = ks * 2 + bKsel;
                    uint32_t boff = (uint32_t)(nrow * 128 + (((kseg ^ (nrow & 7)) << 4)));
                    uint32_t bh[4];
                    ldsm_x4(bh, wb + boff);
#pragma unroll
                    for (int mt = 0; mt < 2; mt++) {
                        mma_f16(acc[mt][np * 2 + 0], ah[mt], &bh[0]);
                        mma_f16(acc[mt][np * 2 + 1], ah[mt], &bh[2]);
                    }
                }
            }
            if (ck + 1 < nchunk) { CP_WAIT0(); __syncthreads(); }
        }
        __syncthreads();

        // ---- epilogue: fp16 C staging with bias, coalesced Y store, fused CAM ----
        __half* Cs = (__half*)smem;
        const float* bsm = (const float*)(smem + SM_BIAS);
#pragma unroll
        for (int mt = 0; mt < 2; mt++) {
#pragma unroll
            for (int nt = 0; nt < 4; nt++) {
                int r0 = wm * 32 + mt * 16 + (lane >> 2);
                int c0 = wn * 32 + nt * 8 + (lane & 3) * 2;
                float b0 = bsm[c0], b1 = bsm[c0 + 1];
                __half2 v0 = __floats2half2_rn(acc[mt][nt][0] + b0, acc[mt][nt][1] + b1);
                __half2 v1 = __floats2half2_rn(acc[mt][nt][2] + b0, acc[mt][nt][3] + b1);
                *(__half2*)&Cs[r0 * CS_STRIDE + c0]       = v0;
                *(__half2*)&Cs[(r0 + 8) * CS_STRIDE + c0] = v1;
            }
        }
        __syncthreads();

        __half* yb = Y + ((size_t)b * HW + hw0) * C_EMB;
        for (int idx = tid; idx < nvalid * 16; idx += 256) {
            int r = idx >> 4;
            int s = idx & 15;
            uint4 v = *(const uint4*)&Cs[r * CS_STRIDE + s * 8];
            *(uint4*)&yb[(size_t)r * C_EMB + s * 8] = v;
        }
        {
            float* redm = (float*)(smem + SM_RED);
            float* reds = redm + 256;
            int c = tid & 127, h = tid >> 7;
            int rs = h ? (nvalid + 1) / 2 : 0;
            int re = h ? nvalid : (nvalid + 1) / 2;
            float mx = -3.4e38f, sm = 0.0f;
            for (int r = rs; r < re; r++) {
                float v = __half2float(Cs[r * CS_STRIDE + c]);
                mx = fmaxf(mx, v);
                sm += v;
            }
            redm[tid] = mx; reds[tid] = sm;
            __syncthreads();       // all Cs reads complete past this point
            if (tid < 128) {
                mx = fmaxf(redm[tid], redm[tid + 128]);
                sm = reds[tid] + reds[tid + 128];
                int o = (scale * NB + b) * C_EMB + tid;
                atomicMax(&g_maxenc[o], encf(mx));
                atomicAdd(&g_sum[o], sm);
            }
        }

        if (t + 1 >= ntiles) break;
        // ---- tile transition: next tile's chunk0 regs -> X buf1; wait W chunk0 ----
        STS_X(xpA, 1);
        CP_WAIT0();
        __syncthreads();
        hw0 += 64;
    }
}

// ---------------- merged gate ----------------
__global__ void gate_all(const float* __restrict__ w1a, const float* __restrict__ b1a,
                         const float* __restrict__ w2a, const float* __restrict__ b2a,
                         const float* __restrict__ w1b, const float* __restrict__ b1b,
                         const float* __restrict__ w2b, const float* __restrict__ b2b,
                         const float* __restrict__ w1c, const float* __restrict__ b1c,
                         const float* __restrict__ w2c, const float* __restrict__ b2c) {
    __shared__ float vmx[C_EMB], vav[C_EMB], hmx[HID], hav[HID], gsh[C_EMB];
    const int scale = blockIdx.x >> 5;
    const int b = blockIdx.x & 31;
    const int c = threadIdx.x;
    const float* w1; const float* b1; const float* w2; const float* b2; int HW;
    if (scale == 0)      { w1 = w1a; b1 = b1a; w2 = w2a; b2 = b2a; HW = HW_0; }
    else if (scale == 1) { w1 = w1b; b1 = b1b; w2 = w2b; b2 = b2b; HW = HW_1; }
    else                 { w1 = w1c; b1 = b1c; w2 = w2c; b2 = b2c; HW = HW_2; }
    const int o = (scale * NB + b) * C_EMB + c;
    vmx[c] = decf(g_maxenc[o]);
    vav[c] = g_sum[o] * (1.0f / (float)HW);
    __syncthreads();
    if (c < HID) {
        float s1 = b1[c], s2 = b1[c];
        for (int k = 0; k < C_EMB; k++) {
            float w = w1[c * C_EMB + k];
            s1 += w * vmx[k];
            s2 += w * vav[k];
        }
        hmx[c] = fmaxf(s1, 0.0f);
        hav[c] = fmaxf(s2, 0.0f);
    }
    __syncthreads();
    float o1 = b2[c], o2 = b2[c];
    for (int k = 0; k < HID; k++) {
        float w = w2[c * HID + k];
        o1 += w * hmx[k];
        o2 += w * hav[k];
    }
    float g = sigmoidf_(o1 + o2);
    g_gate[o] = g;
    gsh[c] = g;
    __syncthreads();
    if (c < C_EMB / 2) {
        __half2 gp = __floats2half2_rn(gsh[2 * c], gsh[2 * c + 1]);
        g_gateh[(scale * NB + b) * (C_EMB / 2) + c] = *(unsigned*)&gp;
    }
}

// ---------------- fused SAM + 7x7 conv + gather (R14, unchanged) ----------------
__global__ void __launch_bounds__(256)
sam_gather(const int* __restrict__ idx, float* __restrict__ out,
           const float* __restrict__ sw0, const float* __restrict__ sw1,
           const float* __restrict__ sw2) {
    __shared__ float wm[98];
    __shared__ float warp_part[8];
    __shared__ float sig_sh;

    const int tid  = threadIdx.x;
    const int wid  = tid >> 5;
    const int lane = tid & 31;
    const int row  = blockIdx.x;
    const int b    = row / KIDX;
    const int id   = idx[row];

    const __half* Y; int HW, SIDE, scale, p;
    if (id < HW_0)              { Y = g_y0s0; HW = HW_0; SIDE = SIDE0; scale = 0; p = id; }
    else if (id < HW_0 + HW_1)  { Y = g_y0s1; HW = HW_1; SIDE = SIDE1; scale = 1; p = id - HW_0; }
    else                        { Y = g_y0s2; HW = HW_2; SIDE = SIDE2; scale = 2; p = id - (HW_0 + HW_1); }

    const float* swsrc = (scale == 0) ? sw0 : (scale == 1) ? sw1 : sw2;
    if (tid < 98) wm[tid] = swsrc[tid];
    __syncthreads();

    const int py = p / SIDE, px = p - py * SIDE;
    const __half* Yb = Y + (size_t)b * HW * C_EMB;

    uint2 gh = *(const uint2*)&g_gateh[(scale * NB + b) * (C_EMB / 2) + lane * 2];
    __half2 gl = *(__half2*)&gh.x;
    __half2 gh2 = *(__half2*)&gh.y;

    uint2 v[7];
    float wmaxr[7], wmeanr[7];
#pragma unroll
    for (int i = 0; i < 7; i++) {
        int n  = wid + 8 * i;
        int nn = (n < 49) ? n : 48;
        int dy = nn / 7 - 3, dx = nn - (nn / 7) * 7 - 3;
        int yy = py + dy, xx = px + dx;
        bool valid = (n < 49) && (yy >= 0) && (yy < SIDE) && (xx >= 0) && (xx < SIDE);
        wmaxr[i]  = (n < 49) ? wm[nn] : 0.0f;
        wmeanr[i] = (n < 49) ? (wm[49 + nn] * (1.0f / (float)C_EMB)) : 0.0f;
        v[i] = make_uint2(0u, 0u);
        if (valid)
            v[i] = *(const uint2*)&Yb[(size_t)(yy * SIDE + xx) * C_EMB + lane * 4];
    }

    float part = 0.0f;
    float mxv[7];
#pragma unroll
    for (int i = 0; i < 7; i++) {
        __half2 p0 = __hmul2(*(__half2*)&v[i].x, gl);
        __half2 p1 = __hmul2(*(__half2*)&v[i].y, gh2);
        float2 f0 = __half22float2(p0), f1 = __half22float2(p1);
        part += ((f0.x + f0.y) + (f1.x + f1.y)) * wmeanr[i];
        __half2 m2 = __hmax2(p0, p1);
        mxv[i] = fmaxf(__half2float(__low2half(m2)), __half2float(__high2half(m2)));
    }
#pragma unroll
    for (int o = 16; o; o >>= 1)
#pragma unroll
        for (int i = 0; i < 7; i++)
            mxv[i] = fmaxf(mxv[i], __shfl_xor_sync(0xFFFFFFFFu, mxv[i], o));
    if (lane == 0) {
#pragma unroll
        for (int i = 0; i < 7; i++) part += mxv[i] * wmaxr[i];
    }
#pragma unroll
    for (int o = 16; o; o >>= 1) part += __shfl_xor_sync(0xFFFFFFFFu, part, o);
    if (lane == 0) warp_part[wid] = part;
    __syncthreads();

    if (wid == 0) {
        float s = (lane < 8) ? warp_part[lane] : 0.0f;
#pragma unroll
        for (int o = 4; o; o >>= 1) s += __shfl_xor_sync(0xFFFFFFFFu, s, o);
        if (lane == 0) sig_sh = sigmoidf_(s);
    }
    __syncthreads();

    if (tid < C_EMB) {
        float sig = sig_sh;
        float y = __half2float(Yb[(size_t)p * C_EMB + tid]);
        float g = g_gate[(scale * NB + b) * C_EMB + tid];
        out[(size_t)row * C_EMB + tid] = y * (1.0f + g * sig);
    }
}

// ---------------- launch ----------------
extern "C" void kernel_launch(void* const* d_in, const int* in_sizes, int n_in,
                              void* d_out, int out_size) {
    const float* x0   = (const float*)d_in[0];
    const float* x1   = (const float*)d_in[1];
    const float* x2   = (const float*)d_in[2];
    const float* yolo = (const float*)d_in[3];
    const int*   ridx = (const int*)d_in[4];
    const float* nw0 = (const float*)d_in[5];
    const float* nb0 = (const float*)d_in[6];
    const float* nw1 = (const float*)d_in[7];
    const float* nb1 = (const float*)d_in[8];
    const float* nw2 = (const float*)d_in[9];
    const float* nb2 = (const float*)d_in[10];
    const float* cw1[3] = {(const float*)d_in[11], (const float*)d_in[16], (const float*)d_in[21]};
    const float* cb1[3] = {(const float*)d_in[12], (const float*)d_in[17], (const float*)d_in[22]};
    const float* cw2[3] = {(const float*)d_in[13], (const float*)d_in[18], (const float*)d_in[23]};
    const float* cb2[3] = {(const float*)d_in[14], (const float*)d_in[19], (const float*)d_in[24]};
    const float* csw[3] = {(const float*)d_in[15], (const float*)d_in[20], (const float*)d_in[25]};

    float* out = (float*)d_out;
    const int yolo_n = NB * 8400 * 6;
    const int emb_n  = NB * KIDX * C_EMB;
    float* emb_out = out;
    if (out_size >= yolo_n + emb_n) {
        cudaMemcpyAsync(out, yolo, (size_t)in_sizes[3] * sizeof(float),
                        cudaMemcpyDeviceToDevice, 0);
        emb_out = out + yolo_n;
    }

    __half *y0p, *y1p, *y2p;
    cudaGetSymbolAddress((void**)&y0p, g_y0s0);
    cudaGetSymbolAddress((void**)&y1p, g_y0s1);
    cudaGetSymbolAddress((void**)&y2p, g_y0s2);
    __half *wh0, *wh1, *wh2;
    cudaGetSymbolAddress((void**)&wh0, g_wh0);
    cudaGetSymbolAddress((void**)&wh1, g_wh1);
    cudaGetSymbolAddress((void**)&wh2, g_wh2);

    cudaFuncSetAttribute((const void*)gemm_all,
                         cudaFuncAttributeMaxDynamicSharedMemorySize, SMEM_GEMM);

    setup_all<<<(NW0 + NW1 + NW2 + 255) / 256, 256>>>(nw0, nw1, nw2);

    gemm_all<<<dim3(82, NB), 256, SMEM_GEMM>>>(
        x0, x1, x2, wh0, wh1, wh2, nb0, nb1, nb2, y0p, y1p, y2p);

    gate_all<<<96, 128>>>(cw1[0], cb1[0], cw2[0], cb2[0],
                          cw1[1], cb1[1], cw2[1], cb2[1],
                          cw1[2], cb1[2], cw2[2], cb2[2]);

    sam_gather<<<NB * KIDX, 256>>>(ridx, emb_out, csw[0], csw[1], csw[2]);
}

// round 16
// speedup vs baseline: 1.4372x; 1.4372x over previous
#include <cuda_runtime.h>
#include <cuda_fp16.h>
#include <cstdint>
#include <math.h>

// ---------------- problem constants ----------------
#define NB 32
#define C_EMB 128
#define HID 32
#define KIDX 100

#define HW_0 6400
#define HW_1 1600
#define HW_2 400
#define SIDE0 80
#define SIDE1 40
#define SIDE2 20

#define NBHW0 (NB * HW_0)
#define NBHW1 (NB * HW_1)
#define NBHW2 (NB * HW_2)

#define NW0 (C_EMB * 256)
#define NW1 (C_EMB * 512)
#define NW2 (C_EMB * 1024)

// ---------------- device scratch ----------------
__device__ __align__(128) __half g_y0s0[(size_t)NBHW0 * C_EMB];
__device__ __align__(128) __half g_y0s1[(size_t)NBHW1 * C_EMB];
__device__ __align__(128) __half g_y0s2[(size_t)NBHW2 * C_EMB];

__device__ __align__(128) __half g_wh0[NW0];
__device__ __align__(128) __half g_wh1[NW1];
__device__ __align__(128) __half g_wh2[NW2];

__device__ unsigned g_maxenc[3 * NB * C_EMB];
__device__ float    g_sum[3 * NB * C_EMB];
__device__ float    g_gate[3 * NB * C_EMB];
__device__ unsigned g_gateh[3 * NB * (C_EMB / 2)];

// ---------------- helpers ----------------
__device__ __forceinline__ uint32_t smem_to_u32(const void* p) {
    uint32_t a;
    asm("{ .reg .u64 t; cvta.to.shared.u64 t, %1; cvt.u32.u64 %0, t; }" : "=r"(a) : "l"(p));
    return a;
}
__device__ __forceinline__ void ldsm_x4(uint32_t* r, uint32_t addr) {
    asm volatile("ldmatrix.sync.aligned.m8n8.x4.shared.b16 {%0,%1,%2,%3}, [%4];"
                 : "=r"(r[0]), "=r"(r[1]), "=r"(r[2]), "=r"(r[3]) : "r"(addr));
}
__device__ __forceinline__ void ldsm_x4_t(uint32_t* r, uint32_t addr) {
    asm volatile("ldmatrix.sync.aligned.m8n8.x4.trans.shared.b16 {%0,%1,%2,%3}, [%4];"
                 : "=r"(r[0]), "=r"(r[1]), "=r"(r[2]), "=r"(r[3]) : "r"(addr));
}
__device__ __forceinline__ void mma_f16(float* d, const uint32_t* a, const uint32_t* b) {
    asm volatile("mma.sync.aligned.m16n8k16.row.col.f32.f16.f16.f32 "
                 "{%0,%1,%2,%3}, {%4,%5,%6,%7}, {%8,%9}, {%0,%1,%2,%3};"
                 : "+f"(d[0]), "+f"(d[1]), "+f"(d[2]), "+f"(d[3])
                 : "r"(a[0]), "r"(a[1]), "r"(a[2]), "r"(a[3]), "r"(b[0]), "r"(b[1]));
}
__device__ __forceinline__ void cp_async16(uint32_t saddr, const void* gptr) {
    asm volatile("cp.async.cg.shared.global [%0], [%1], 16;" :: "r"(saddr), "l"(gptr));
}
#define CP_COMMIT() asm volatile("cp.async.commit_group;" ::: "memory")
#define CP_WAIT0()  asm volatile("cp.async.wait_group 0;"  ::: "memory")

__device__ __forceinline__ unsigned encf(float f) {
    unsigned u = __float_as_uint(f);
    return (u & 0x80000000u) ? ~u : (u | 0x80000000u);
}
__device__ __forceinline__ float decf(unsigned e) {
    return (e & 0x80000000u) ? __uint_as_float(e & 0x7FFFFFFFu) : __uint_as_float(~e);
}
__device__ __forceinline__ float sigmoidf_(float x) { return 1.0f / (1.0f + __expf(-x)); }

// ---------------- setup ----------------
__global__ void setup_all(const float* __restrict__ nw0, const float* __restrict__ nw1,
                          const float* __restrict__ nw2) {
    int i = blockIdx.x * 256 + threadIdx.x;
    if (i < 3 * NB * C_EMB) { g_maxenc[i] = 0u; g_sum[i] = 0.0f; }
    if (i < NW0)                  g_wh0[i] = __float2half_rn(nw0[i]);
    else if (i < NW0 + NW1)       g_wh1[i - NW0] = __float2half_rn(nw1[i - NW0]);
    else if (i < NW0 + NW1 + NW2) g_wh2[i - NW0 - NW1] = __float2half_rn(nw2[i - NW0 - NW1]);
}

// ---------------- merged HMMA GEMM: 64hw x 128ch tile, 3 CTAs/SM ----------------
static constexpr int SM_XB0  = 0;
static constexpr int SM_WB0  = 16384;
static constexpr int SM_BIAS = 49152;
static constexpr int SM_RED  = 49664;
static constexpr int SMEM_GEMM = 49664 + 2048;
static constexpr int CS_STRIDE = 136;

__global__ void __launch_bounds__(256, 3)
gemm_all(const float* __restrict__ x0, const float* __restrict__ x1, const float* __restrict__ x2,
         const __half* __restrict__ wh0, const __half* __restrict__ wh1, const __half* __restrict__ wh2,
         const float* __restrict__ nb0, const float* __restrict__ nb1, const float* __restrict__ nb2,
         __half* __restrict__ y0, __half* __restrict__ y1, __half* __restrict__ y2) {
    extern __shared__ __align__(128) char smem[];
    const uint32_t sb = smem_to_u32(smem);
    const int tid  = threadIdx.x;
    const int lane = tid & 31;
    const int wid  = tid >> 5;
    const int wm   = wid & 1;
    const int wn   = wid >> 1;
    const int b    = blockIdx.y;

    const float* X; const __half* Wh; const float* bias; __half* Y;
    int CIN, HW, scale, tile;
    int bx = blockIdx.x;
    if (bx < 7)       { scale = 2; tile = bx;      X = x2; Wh = wh2; bias = nb2; Y = y2; CIN = 1024; HW = HW_2; }
    else if (bx < 32) { scale = 1; tile = bx - 7;  X = x1; Wh = wh1; bias = nb1; Y = y1; CIN = 512;  HW = HW_1; }
    else              { scale = 0; tile = bx - 32; X = x0; Wh = wh0; bias = nb0; Y = y0; CIN = 256;  HW = HW_0; }
    const int hw0 = tile * 64;
    int nvalid = HW - hw0; if (nvalid > 64) nvalid = 64;
    const int nchunk = CIN >> 6;

    if (tid < 32) ((float4*)(smem + SM_BIAS))[tid] = ((const float4*)bias)[tid];

    const int ti = lane & 7;
    const int gq = lane >> 3;
    const int aKrow = ((gq >> 1) << 3) + ti;
    const int aMsel = (gq & 1) << 3;
    const int bKsel = gq & 1;
    const int bNrow = ((gq >> 1) << 3) + ti;

    uint32_t offA[2];
#pragma unroll
    for (int mt = 0; mt < 2; mt++) {
        int m0 = wm * 32 + mt * 16 + aMsel;
        offA[mt] = (uint32_t)(aKrow * 128 + ((((m0 >> 3) ^ (aKrow & 7)) << 4)));
    }

    float acc[2][4][4];
#pragma unroll
    for (int mt = 0; mt < 2; mt++)
#pragma unroll
        for (int nt = 0; nt < 4; nt++)
#pragma unroll
            for (int r = 0; r < 4; r++) acc[mt][nt][r] = 0.0f;

    const int xr  = tid >> 2;
    const int xc0 = tid & 3;
    const float* xbase = X + ((size_t)b * CIN) * HW + hw0;

    uint2 xpA[4], xpB[4];

#define LDG_X(K0, SET) do { \
        const float* row_ = xbase + (size_t)((K0) + xr) * HW; \
        _Pragma("unroll") \
        for (int i_ = 0; i_ < 4; i_++) { \
            int c4_ = xc0 + 4 * i_; \
            int hwb_ = c4_ * 4; \
            float4 v_ = (hw0 + hwb_ < HW) ? *(const float4*)(row_ + hwb_) \
                                          : make_float4(0.f, 0.f, 0.f, 0.f); \
            __half2 p0_ = __floats2half2_rn(v_.x, v_.y); \
            __half2 p1_ = __floats2half2_rn(v_.z, v_.w); \
            (SET)[i_] = make_uint2(*(uint32_t*)&p0_, *(uint32_t*)&p1_); \
        } \
    } while (0)

#define STS_X(SET, BUF) do { \
        uint32_t base_ = sb + SM_XB0 + (BUF) * 8192; \
        _Pragma("unroll") \
        for (int i_ = 0; i_ < 4; i_++) { \
            int c4_ = xc0 + 4 * i_; \
            uint32_t off_ = (uint32_t)(xr * 128 + ((((c4_ >> 1) ^ (xr & 7)) << 4)) + (c4_ & 1) * 8); \
            asm volatile("st.shared.v2.b32 [%0], {%1, %2};" :: "r"(base_ + off_), "r"((SET)[i_].x), "r"((SET)[i_].y)); \
        } \
    } while (0)

#define CPA_W(K0, BUF) do { \
        uint32_t wb_ = sb + SM_WB0 + (BUF) * 16384; \
        _Pragma("unroll") \
        for (int i_ = 0; i_ < 4; i_++) { \
            int idx_ = tid + i_ * 256; \
            int n_   = idx_ >> 3; \
            int seg_ = idx_ & 7; \
            uint32_t off_ = (uint32_t)(n_ * 128 + ((seg_ ^ (n_ & 7)) << 4)); \
            cp_async16(wb_ + off_, Wh + (size_t)n_ * CIN + (K0) + seg_ * 8); \
        } \
    } while (0)

    // prologue
    CPA_W(0, 0);
    CP_COMMIT();
    LDG_X(0, xpA);
    STS_X(xpA, 0);
    LDG_X(64, xpB);
    CP_WAIT0();
    __syncthreads();

    for (int ck = 0; ; ck++) {
        const int cur = ck & 1;
        const int nxt = cur ^ 1;
        if (ck + 1 < nchunk) {
            if (cur) STS_X(xpA, nxt); else STS_X(xpB, nxt);
            CPA_W((ck + 1) * 64, nxt);
            CP_COMMIT();
        }
        if (ck + 2 < nchunk) { if (cur) LDG_X((ck + 2) * 64, xpB); else LDG_X((ck + 2) * 64, xpA); }

        const uint32_t xb = sb + SM_XB0 + cur * 8192;
        const uint32_t wb = sb + SM_WB0 + cur * 16384;
#pragma unroll
        for (int ks = 0; ks < 4; ks++) {
            const uint32_t kb = (uint32_t)(ks * 16 * 128);
            uint32_t ah[2][4];
            ldsm_x4_t(ah[0], xb + kb + offA[0]);
            ldsm_x4_t(ah[1], xb + kb + offA[1]);
#pragma unroll
            for (int np = 0; np < 2; np++) {
                int nrow = wn * 32 + np * 16 + bNrow;
                int kseg = ks * 2 + bKsel;
                uint32_t boff = (uint32_t)(nrow * 128 + (((kseg ^ (nrow & 7)) << 4)));
                uint32_t bh[4];
                ldsm_x4(bh, wb + boff);
#pragma unroll
                for (int mt = 0; mt < 2; mt++) {
                    mma_f16(acc[mt][np * 2 + 0], ah[mt], &bh[0]);
                    mma_f16(acc[mt][np * 2 + 1], ah[mt], &bh[2]);
                }
            }
        }
        if (ck + 1 >= nchunk) break;
        CP_WAIT0();
        __syncthreads();
    }
    __syncthreads();

    // epilogue
    __half* Cs = (__half*)smem;
    const float* bsm = (const float*)(smem + SM_BIAS);
#pragma unroll
    for (int mt = 0; mt < 2; mt++) {
#pragma unroll
        for (int nt = 0; nt < 4; nt++) {
            int r0 = wm * 32 + mt * 16 + (lane >> 2);
            int c0 = wn * 32 + nt * 8 + (lane & 3) * 2;
            float b0 = bsm[c0], b1 = bsm[c0 + 1];
            __half2 v0 = __floats2half2_rn(acc[mt][nt][0] + b0, acc[mt][nt][1] + b1);
            __half2 v1 = __floats2half2_rn(acc[mt][nt][2] + b0, acc[mt][nt][3] + b1);
            *(__half2*)&Cs[r0 * CS_STRIDE + c0]       = v0;
            *(__half2*)&Cs[(r0 + 8) * CS_STRIDE + c0] = v1;
        }
    }
    __syncthreads();

    __half* yb = Y + ((size_t)b * HW + hw0) * C_EMB;
    for (int idx = tid; idx < nvalid * 16; idx += 256) {
        int r = idx >> 4;
        int s = idx & 15;
        uint4 v = *(const uint4*)&Cs[r * CS_STRIDE + s * 8];
        *(uint4*)&yb[(size_t)r * C_EMB + s * 8] = v;
    }
    {
        float* redm = (float*)(smem + SM_RED);
        float* reds = redm + 256;
        int c = tid & 127, h = tid >> 7;
        int rs = h ? (nvalid + 1) / 2 : 0;
        int re = h ? nvalid : (nvalid + 1) / 2;
        float mx = -3.4e38f, sm = 0.0f;
        for (int r = rs; r < re; r++) {
            float v = __half2float(Cs[r * CS_STRIDE + c]);
            mx = fmaxf(mx, v);
            sm += v;
        }
        redm[tid] = mx; reds[tid] = sm;
        __syncthreads();
        if (tid < 128) {
            mx = fmaxf(redm[tid], redm[tid + 128]);
            sm = reds[tid] + reds[tid + 128];
            int o = (scale * NB + b) * C_EMB + tid;
            atomicMax(&g_maxenc[o], encf(mx));
            atomicAdd(&g_sum[o], sm);
        }
    }
}

// ---------------- merged gate ----------------
__global__ void gate_all(const float* __restrict__ w1a, const float* __restrict__ b1a,
                         const float* __restrict__ w2a, const float* __restrict__ b2a,
                         const float* __restrict__ w1b, const float* __restrict__ b1b,
                         const float* __restrict__ w2b, const float* __restrict__ b2b,
                         const float* __restrict__ w1c, const float* __restrict__ b1c,
                         const float* __restrict__ w2c, const float* __restrict__ b2c) {
    __shared__ float vmx[C_EMB], vav[C_EMB], hmx[HID], hav[HID], gsh[C_EMB];
    const int scale = blockIdx.x >> 5;
    const int b = blockIdx.x & 31;
    const int c = threadIdx.x;
    const float* w1; const float* b1; const float* w2; const float* b2; int HW;
    if (scale == 0)      { w1 = w1a; b1 = b1a; w2 = w2a; b2 = b2a; HW = HW_0; }
    else if (scale == 1) { w1 = w1b; b1 = b1b; w2 = w2b; b2 = b2b; HW = HW_1; }
    else                 { w1 = w1c; b1 = b1c; w2 = w2c; b2 = b2c; HW = HW_2; }
    const int o = (scale * NB + b) * C_EMB + c;
    vmx[c] = decf(g_maxenc[o]);
    vav[c] = g_sum[o] * (1.0f / (float)HW);
    __syncthreads();
    if (c < HID) {
        float s1 = b1[c], s2 = b1[c];
        for (int k = 0; k < C_EMB; k++) {
            float w = w1[c * C_EMB + k];
            s1 += w * vmx[k];
            s2 += w * vav[k];
        }
        hmx[c] = fmaxf(s1, 0.0f);
        hav[c] = fmaxf(s2, 0.0f);
    }
    __syncthreads();
    float o1 = b2[c], o2 = b2[c];
    for (int k = 0; k < HID; k++) {
        float w = w2[c * HID + k];
        o1 += w * hmx[k];
        o2 += w * hav[k];
    }
    float g = sigmoidf_(o1 + o2);
    g_gate[o] = g;
    gsh[c] = g;
    __syncthreads();
    if (c < C_EMB / 2) {
        __half2 gp = __floats2half2_rn(gsh[2 * c], gsh[2 * c + 1]);
        g_gateh[(scale * NB + b) * (C_EMB / 2) + c] = *(unsigned*)&gp;
    }
}

// ---------------- fused SAM + 7x7 conv + gather (prefetched, ILP reductions) ----------------
__global__ void __launch_bounds__(256)
sam_gather(const int* __restrict__ idx, float* __restrict__ out,
           const float* __restrict__ sw0, const float* __restrict__ sw1,
           const float* __restrict__ sw2) {
    __shared__ float wm[98];
    __shared__ float warp_part[8];
    __shared__ float sig_sh;

    const int tid  = threadIdx.x;
    const int wid  = tid >> 5;
    const int lane = tid & 31;
    const int row  = blockIdx.x;
    const int b    = row / KIDX;
    const int id   = idx[row];

    const __half* Y; int HW, SIDE, scale, p;
    if (id < HW_0)              { Y = g_y0s0; HW = HW_0; SIDE = SIDE0; scale = 0; p = id; }
    else if (id < HW_0 + HW_1)  { Y = g_y0s1; HW = HW_1; SIDE = SIDE1; scale = 1; p = id - HW_0; }
    else                        { Y = g_y0s2; HW = HW_2; SIDE = SIDE2; scale = 2; p = id - (HW_0 + HW_1); }

    const float* swsrc = (scale == 0) ? sw0 : (scale == 1) ? sw1 : sw2;
    if (tid < 98) wm[tid] = swsrc[tid];
    __syncthreads();

    const int py = p / SIDE, px = p - py * SIDE;
    const __half* Yb = Y + (size_t)b * HW * C_EMB;

    uint2 gh = *(const uint2*)&g_gateh[(scale * NB + b) * (C_EMB / 2) + lane * 2];
    __half2 gl = *(__half2*)&gh.x;
    __half2 gh2 = *(__half2*)&gh.y;

    // ---- phase 1: prefetch all (up to 7) neighbor rows for this warp ----
    uint2 v[7];
    float wmaxr[7], wmeanr[7];
#pragma unroll
    for (int i = 0; i < 7; i++) {
        int n  = wid + 8 * i;
        int nn = (n < 49) ? n : 48;
        int dy = nn / 7 - 3, dx = nn - (nn / 7) * 7 - 3;
        int yy = py + dy, xx = px + dx;
        bool valid = (n < 49) && (yy >= 0) && (yy < SIDE) && (xx >= 0) && (xx < SIDE);
        wmaxr[i]  = (n < 49) ? wm[nn] : 0.0f;
        wmeanr[i] = (n < 49) ? (wm[49 + nn] * (1.0f / (float)C_EMB)) : 0.0f;
        v[i] = make_uint2(0u, 0u);
        if (valid)
            v[i] = *(const uint2*)&Yb[(size_t)(yy * SIDE + xx) * C_EMB + lane * 4];
    }

    // ---- phase 2: products + per-lane maxima + weighted mean accumulation ----
    float part = 0.0f;
    float mxv[7];
#pragma unroll
    for (int i = 0; i < 7; i++) {
        __half2 p0 = __hmul2(*(__half2*)&v[i].x, gl);
        __half2 p1 = __hmul2(*(__half2*)&v[i].y, gh2);
        float2 f0 = __half22float2(p0), f1 = __half22float2(p1);
        part += ((f0.x + f0.y) + (f1.x + f1.y)) * wmeanr[i];
        __half2 m2 = __hmax2(p0, p1);
        mxv[i] = fmaxf(__half2float(__low2half(m2)), __half2float(__high2half(m2)));
    }
    // ---- phase 3: interleaved butterfly max over all 7 values (ILP) ----
#pragma unroll
    for (int o = 16; o; o >>= 1)
#pragma unroll
        for (int i = 0; i < 7; i++)
            mxv[i] = fmaxf(mxv[i], __shfl_xor_sync(0xFFFFFFFFu, mxv[i], o));
    if (lane == 0) {
#pragma unroll
        for (int i = 0; i < 7; i++) part += mxv[i] * wmaxr[i];
    }
    // single warp-sum of part
#pragma unroll
    for (int o = 16; o; o >>= 1) part += __shfl_xor_sync(0xFFFFFFFFu, part, o);
    if (lane == 0) warp_part[wid] = part;
    __syncthreads();

    if (wid == 0) {
        float s = (lane < 8) ? warp_part[lane] : 0.0f;
#pragma unroll
        for (int o = 4; o; o >>= 1) s += __shfl_xor_sync(0xFFFFFFFFu, s, o);
        if (lane == 0) sig_sh = sigmoidf_(s);
    }
    __syncthreads();

    if (tid < C_EMB) {
        float sig = sig_sh;
        float y = __half2float(Yb[(size_t)p * C_EMB + tid]);
        float g = g_gate[(scale * NB + b) * C_EMB + tid];
        out[(size_t)row * C_EMB + tid] = y * (1.0f + g * sig);
    }
}

// ---------------- launch ----------------
extern "C" void kernel_launch(void* const* d_in, const int* in_sizes, int n_in,
                              void* d_out, int out_size) {
    const float* x0   = (const float*)d_in[0];
    const float* x1   = (const float*)d_in[1];
    const float* x2   = (const float*)d_in[2];
    const float* yolo = (const float*)d_in[3];
    const int*   ridx = (const int*)d_in[4];
    const float* nw0 = (const float*)d_in[5];
    const float* nb0 = (const float*)d_in[6];
    const float* nw1 = (const float*)d_in[7];
    const float* nb1 = (const float*)d_in[8];
    const float* nw2 = (const float*)d_in[9];
    const float* nb2 = (const float*)d_in[10];
    const float* cw1[3] = {(const float*)d_in[11], (const float*)d_in[16], (const float*)d_in[21]};
    const float* cb1[3] = {(const float*)d_in[12], (const float*)d_in[17], (const float*)d_in[22]};
    const float* cw2[3] = {(const float*)d_in[13], (const float*)d_in[18], (const float*)d_in[23]};
    const float* cb2[3] = {(const float*)d_in[14], (const float*)d_in[19], (const float*)d_in[24]};
    const float* csw[3] = {(const float*)d_in[15], (const float*)d_in[20], (const float*)d_in[25]};

    float* out = (float*)d_out;
    const int yolo_n = NB * 8400 * 6;
    const int emb_n  = NB * KIDX * C_EMB;
    float* emb_out = out;
    if (out_size >= yolo_n + emb_n) {
        cudaMemcpyAsync(out, yolo, (size_t)in_sizes[3] * sizeof(float),
                        cudaMemcpyDeviceToDevice, 0);
        emb_out = out + yolo_n;
    }

    __half *y0p, *y1p, *y2p;
    cudaGetSymbolAddress((void**)&y0p, g_y0s0);
    cudaGetSymbolAddress((void**)&y1p, g_y0s1);
    cudaGetSymbolAddress((void**)&y2p, g_y0s2);
    __half *wh0, *wh1, *wh2;
    cudaGetSymbolAddress((void**)&wh0, g_wh0);
    cudaGetSymbolAddress((void**)&wh1, g_wh1);
    cudaGetSymbolAddress((void**)&wh2, g_wh2);

    cudaFuncSetAttribute((const void*)gemm_all,
                         cudaFuncAttributeMaxDynamicSharedMemorySize, SMEM_GEMM);

    setup_all<<<(NW0 + NW1 + NW2 + 255) / 256, 256>>>(nw0, nw1, nw2);

    gemm_all<<<dim3(132, NB), 256, SMEM_GEMM>>>(
        x0, x1, x2, wh0, wh1, wh2, nb0, nb1, nb2, y0p, y1p, y2p);

    gate_all<<<96, 128>>>(cw1[0], cb1[0], cw2[0], cb2[0],
                          cw1[1], cb1[1], cw2[1], cb2[1],
                          cw1[2], cb1[2], cw2[2], cb2[2]);

    sam_gather<<<NB * KIDX, 256>>>(ridx, emb_out, csw[0], csw[1], csw[2]);
}

// round 17
// speedup vs baseline: 1.4762x; 1.0272x over previous
#include <cuda_runtime.h>
#include <cuda_fp16.h>
#include <cstdint>
#include <math.h>

// ---------------- problem constants ----------------
#define NB 32
#define C_EMB 128
#define HID 32
#define KIDX 100

#define HW_0 6400
#define HW_1 1600
#define HW_2 400
#define SIDE0 80
#define SIDE1 40
#define SIDE2 20

#define NBHW0 (NB * HW_0)
#define NBHW1 (NB * HW_1)
#define NBHW2 (NB * HW_2)

#define NW0 (C_EMB * 256)
#define NW1 (C_EMB * 512)
#define NW2 (C_EMB * 1024)

// ---------------- device scratch ----------------
__device__ __align__(128) __half g_y0s0[(size_t)NBHW0 * C_EMB];
__device__ __align__(128) __half g_y0s1[(size_t)NBHW1 * C_EMB];
__device__ __align__(128) __half g_y0s2[(size_t)NBHW2 * C_EMB];

__device__ __align__(128) __half g_wh0[NW0];
__device__ __align__(128) __half g_wh1[NW1];
__device__ __align__(128) __half g_wh2[NW2];

__device__ unsigned g_maxenc[3 * NB * C_EMB];
__device__ float    g_sum[3 * NB * C_EMB];
__device__ float    g_gate[3 * NB * C_EMB];
__device__ unsigned g_gateh[3 * NB * (C_EMB / 2)];

// ---------------- helpers ----------------
__device__ __forceinline__ uint32_t smem_to_u32(const void* p) {
    uint32_t a;
    asm("{ .reg .u64 t; cvta.to.shared.u64 t, %1; cvt.u32.u64 %0, t; }" : "=r"(a) : "l"(p));
    return a;
}
__device__ __forceinline__ void ldsm_x4(uint32_t* r, uint32_t addr) {
    asm volatile("ldmatrix.sync.aligned.m8n8.x4.shared.b16 {%0,%1,%2,%3}, [%4];"
                 : "=r"(r[0]), "=r"(r[1]), "=r"(r[2]), "=r"(r[3]) : "r"(addr));
}
__device__ __forceinline__ void ldsm_x4_t(uint32_t* r, uint32_t addr) {
    asm volatile("ldmatrix.sync.aligned.m8n8.x4.trans.shared.b16 {%0,%1,%2,%3}, [%4];"
                 : "=r"(r[0]), "=r"(r[1]), "=r"(r[2]), "=r"(r[3]) : "r"(addr));
}
__device__ __forceinline__ void mma_f16(float* d, const uint32_t* a, const uint32_t* b) {
    asm volatile("mma.sync.aligned.m16n8k16.row.col.f32.f16.f16.f32 "
                 "{%0,%1,%2,%3}, {%4,%5,%6,%7}, {%8,%9}, {%0,%1,%2,%3};"
                 : "+f"(d[0]), "+f"(d[1]), "+f"(d[2]), "+f"(d[3])
                 : "r"(a[0]), "r"(a[1]), "r"(a[2]), "r"(a[3]), "r"(b[0]), "r"(b[1]));
}
__device__ __forceinline__ void cp_async16(uint32_t saddr, const void* gptr) {
    asm volatile("cp.async.cg.shared.global [%0], [%1], 16;" :: "r"(saddr), "l"(gptr));
}
#define CP_COMMIT() asm volatile("cp.async.commit_group;" ::: "memory")
#define CP_WAIT0()  asm volatile("cp.async.wait_group 0;"  ::: "memory")

__device__ __forceinline__ unsigned encf(float f) {
    unsigned u = __float_as_uint(f);
    return (u & 0x80000000u) ? ~u : (u | 0x80000000u);
}
__device__ __forceinline__ float decf(unsigned e) {
    return (e & 0x80000000u) ? __uint_as_float(e & 0x7FFFFFFFu) : __uint_as_float(~e);
}
__device__ __forceinline__ float sigmoidf_(float x) { return 1.0f / (1.0f + __expf(-x)); }

// ---------------- setup: stats init + W fp32->fp16, 2 elems/thread ----------------
__global__ void setup_all(const float* __restrict__ nw0, const float* __restrict__ nw1,
                          const float* __restrict__ nw2) {
    int i = blockIdx.x * 256 + threadIdx.x;
    if (i < 3 * NB * C_EMB) { g_maxenc[i] = 0u; g_sum[i] = 0.0f; }
    int j = i * 2;
    const float* src; __half* dst;
    if (j < NW0)                  { src = nw0 + j;               dst = g_wh0 + j; }
    else if (j < NW0 + NW1)       { src = nw1 + (j - NW0);       dst = g_wh1 + (j - NW0); }
    else if (j < NW0 + NW1 + NW2) { src = nw2 + (j - NW0 - NW1); dst = g_wh2 + (j - NW0 - NW1); }
    else return;
    float2 v = *(const float2*)src;
    __half2 h = __floats2half2_rn(v.x, v.y);
    *(__half2*)dst = h;
}

// ---------------- merged HMMA GEMM: 64hw x 128ch tile, 3 CTAs/SM (R16, unchanged) ----------------
static constexpr int SM_XB0  = 0;
static constexpr int SM_WB0  = 16384;
static constexpr int SM_BIAS = 49152;
static constexpr int SM_RED  = 49664;
static constexpr int SMEM_GEMM = 49664 + 2048;
static constexpr int CS_STRIDE = 136;

__global__ void __launch_bounds__(256, 3)
gemm_all(const float* __restrict__ x0, const float* __restrict__ x1, const float* __restrict__ x2,
         const __half* __restrict__ wh0, const __half* __restrict__ wh1, const __half* __restrict__ wh2,
         const float* __restrict__ nb0, const float* __restrict__ nb1, const float* __restrict__ nb2,
         __half* __restrict__ y0, __half* __restrict__ y1, __half* __restrict__ y2) {
    extern __shared__ __align__(128) char smem[];
    const uint32_t sb = smem_to_u32(smem);
    const int tid  = threadIdx.x;
    const int lane = tid & 31;
    const int wid  = tid >> 5;
    const int wm   = wid & 1;
    const int wn   = wid >> 1;
    const int b    = blockIdx.y;

    const float* X; const __half* Wh; const float* bias; __half* Y;
    int CIN, HW, scale, tile;
    int bx = blockIdx.x;
    if (bx < 7)       { scale = 2; tile = bx;      X = x2; Wh = wh2; bias = nb2; Y = y2; CIN = 1024; HW = HW_2; }
    else if (bx < 32) { scale = 1; tile = bx - 7;  X = x1; Wh = wh1; bias = nb1; Y = y1; CIN = 512;  HW = HW_1; }
    else              { scale = 0; tile = bx - 32; X = x0; Wh = wh0; bias = nb0; Y = y0; CIN = 256;  HW = HW_0; }
    const int hw0 = tile * 64;
    int nvalid = HW - hw0; if (nvalid > 64) nvalid = 64;
    const int nchunk = CIN >> 6;

    if (tid < 32) ((float4*)(smem + SM_BIAS))[tid] = ((const float4*)bias)[tid];

    const int ti = lane & 7;
    const int gq = lane >> 3;
    const int aKrow = ((gq >> 1) << 3) + ti;
    const int aMsel = (gq & 1) << 3;
    const int bKsel = gq & 1;
    const int bNrow = ((gq >> 1) << 3) + ti;

    uint32_t offA[2];
#pragma unroll
    for (int mt = 0; mt < 2; mt++) {
        int m0 = wm * 32 + mt * 16 + aMsel;
        offA[mt] = (uint32_t)(aKrow * 128 + ((((m0 >> 3) ^ (aKrow & 7)) << 4)));
    }

    float acc[2][4][4];
#pragma unroll
    for (int mt = 0; mt < 2; mt++)
#pragma unroll
        for (int nt = 0; nt < 4; nt++)
#pragma unroll
            for (int r = 0; r < 4; r++) acc[mt][nt][r] = 0.0f;

    const int xr  = tid >> 2;
    const int xc0 = tid & 3;
    const float* xbase = X + ((size_t)b * CIN) * HW + hw0;

    uint2 xpA[4], xpB[4];

#define LDG_X(K0, SET) do { \
        const float* row_ = xbase + (size_t)((K0) + xr) * HW; \
        _Pragma("unroll") \
        for (int i_ = 0; i_ < 4; i_++) { \
            int c4_ = xc0 + 4 * i_; \
            int hwb_ = c4_ * 4; \
            float4 v_ = (hw0 + hwb_ < HW) ? *(const float4*)(row_ + hwb_) \
                                          : make_float4(0.f, 0.f, 0.f, 0.f); \
            __half2 p0_ = __floats2half2_rn(v_.x, v_.y); \
            __half2 p1_ = __floats2half2_rn(v_.z, v_.w); \
            (SET)[i_] = make_uint2(*(uint32_t*)&p0_, *(uint32_t*)&p1_); \
        } \
    } while (0)

#define STS_X(SET, BUF) do { \
        uint32_t base_ = sb + SM_XB0 + (BUF) * 8192; \
        _Pragma("unroll") \
        for (int i_ = 0; i_ < 4; i_++) { \
            int c4_ = xc0 + 4 * i_; \
            uint32_t off_ = (uint32_t)(xr * 128 + ((((c4_ >> 1) ^ (xr & 7)) << 4)) + (c4_ & 1) * 8); \
            asm volatile("st.shared.v2.b32 [%0], {%1, %2};" :: "r"(base_ + off_), "r"((SET)[i_].x), "r"((SET)[i_].y)); \
        } \
    } while (0)

#define CPA_W(K0, BUF) do { \
        uint32_t wb_ = sb + SM_WB0 + (BUF) * 16384; \
        _Pragma("unroll") \
        for (int i_ = 0; i_ < 4; i_++) { \
            int idx_ = tid + i_ * 256; \
            int n_   = idx_ >> 3; \
            int seg_ = idx_ & 7; \
            uint32_t off_ = (uint32_t)(n_ * 128 + ((seg_ ^ (n_ & 7)) << 4)); \
            cp_async16(wb_ + off_, Wh + (size_t)n_ * CIN + (K0) + seg_ * 8); \
        } \
    } while (0)

    // prologue
    CPA_W(0, 0);
    CP_COMMIT();
    LDG_X(0, xpA);
    STS_X(xpA, 0);
    LDG_X(64, xpB);
    CP_WAIT0();
    __syncthreads();

    for (int ck = 0; ; ck++) {
        const int cur = ck & 1;
        const int nxt = cur ^ 1;
        if (ck + 1 < nchunk) {
            if (cur) STS_X(xpA, nxt); else STS_X(xpB, nxt);
            CPA_W((ck + 1) * 64, nxt);
            CP_COMMIT();
        }
        if (ck + 2 < nchunk) { if (cur) LDG_X((ck + 2) * 64, xpB); else LDG_X((ck + 2) * 64, xpA); }

        const uint32_t xb = sb + SM_XB0 + cur * 8192;
        const uint32_t wb = sb + SM_WB0 + cur * 16384;
#pragma unroll
        for (int ks = 0; ks < 4; ks++) {
            const uint32_t kb = (uint32_t)(ks * 16 * 128);
            uint32_t ah[2][4];
            ldsm_x4_t(ah[0], xb + kb + offA[0]);
            ldsm_x4_t(ah[1], xb + kb + offA[1]);
#pragma unroll
            for (int np = 0; np < 2; np++) {
                int nrow = wn * 32 + np * 16 + bNrow;
                int kseg = ks * 2 + bKsel;
                uint32_t boff = (uint32_t)(nrow * 128 + (((kseg ^ (nrow & 7)) << 4)));
                uint32_t bh[4];
                ldsm_x4(bh, wb + boff);
#pragma unroll
                for (int mt = 0; mt < 2; mt++) {
                    mma_f16(acc[mt][np * 2 + 0], ah[mt], &bh[0]);
                    mma_f16(acc[mt][np * 2 + 1], ah[mt], &bh[2]);
                }
            }
        }
        if (ck + 1 >= nchunk) break;
        CP_WAIT0();
        __syncthreads();
    }
    __syncthreads();

    // epilogue
    __half* Cs = (__half*)smem;
    const float* bsm = (const float*)(smem + SM_BIAS);
#pragma unroll
    for (int mt = 0; mt < 2; mt++) {
#pragma unroll
        for (int nt = 0; nt < 4; nt++) {
            int r0 = wm * 32 + mt * 16 + (lane >> 2);
            int c0 = wn * 32 + nt * 8 + (lane & 3) * 2;
            float b0 = bsm[c0], b1 = bsm[c0 + 1];
            __half2 v0 = __floats2half2_rn(acc[mt][nt][0] + b0, acc[mt][nt][1] + b1);
            __half2 v1 = __floats2half2_rn(acc[mt][nt][2] + b0, acc[mt][nt][3] + b1);
            *(__half2*)&Cs[r0 * CS_STRIDE + c0]       = v0;
            *(__half2*)&Cs[(r0 + 8) * CS_STRIDE + c0] = v1;
        }
    }
    __syncthreads();

    __half* yb = Y + ((size_t)b * HW + hw0) * C_EMB;
    for (int idx = tid; idx < nvalid * 16; idx += 256) {
        int r = idx >> 4;
        int s = idx & 15;
        uint4 v = *(const uint4*)&Cs[r * CS_STRIDE + s * 8];
        *(uint4*)&yb[(size_t)r * C_EMB + s * 8] = v;
    }
    {
        float* redm = (float*)(smem + SM_RED);
        float* reds = redm + 256;
        int c = tid & 127, h = tid >> 7;
        int rs = h ? (nvalid + 1) / 2 : 0;
        int re = h ? nvalid : (nvalid + 1) / 2;
        float mx = -3.4e38f, sm = 0.0f;
        for (int r = rs; r < re; r++) {
            float v = __half2float(Cs[r * CS_STRIDE + c]);
            mx = fmaxf(mx, v);
            sm += v;
        }
        redm[tid] = mx; reds[tid] = sm;
        __syncthreads();
        if (tid < 128) {
            mx = fmaxf(redm[tid], redm[tid + 128]);
            sm = reds[tid] + reds[tid + 128];
            int o = (scale * NB + b) * C_EMB + tid;
            atomicMax(&g_maxenc[o], encf(mx));
            atomicAdd(&g_sum[o], sm);
        }
    }
}

// ---------------- merged gate ----------------
__global__ void gate_all(const float* __restrict__ w1a, const float* __restrict__ b1a,
                         const float* __restrict__ w2a, const float* __restrict__ b2a,
                         const float* __restrict__ w1b, const float* __restrict__ b1b,
                         const float* __restrict__ w2b, const float* __restrict__ b2b,
                         const float* __restrict__ w1c, const float* __restrict__ b1c,
                         const float* __restrict__ w2c, const float* __restrict__ b2c) {
    __shared__ float vmx[C_EMB], vav[C_EMB], hmx[HID], hav[HID], gsh[C_EMB];
    const int scale = blockIdx.x >> 5;
    const int b = blockIdx.x & 31;
    const int c = threadIdx.x;
    const float* w1; const float* b1; const float* w2; const float* b2; int HW;
    if (scale == 0)      { w1 = w1a; b1 = b1a; w2 = w2a; b2 = b2a; HW = HW_0; }
    else if (scale == 1) { w1 = w1b; b1 = b1b; w2 = w2b; b2 = b2b; HW = HW_1; }
    else                 { w1 = w1c; b1 = b1c; w2 = w2c; b2 = b2c; HW = HW_2; }
    const int o = (scale * NB + b) * C_EMB + c;
    vmx[c] = decf(g_maxenc[o]);
    vav[c] = g_sum[o] * (1.0f / (float)HW);
    __syncthreads();
    if (c < HID) {
        float s1 = b1[c], s2 = b1[c];
        for (int k = 0; k < C_EMB; k++) {
            float w = w1[c * C_EMB + k];
            s1 += w * vmx[k];
            s2 += w * vav[k];
        }
        hmx[c] = fmaxf(s1, 0.0f);
        hav[c] = fmaxf(s2, 0.0f);
    }
    __syncthreads();
    float o1 = b2[c], o2 = b2[c];
    for (int k = 0; k < HID; k++) {
        float w = w2[c * HID + k];
        o1 += w * hmx[k];
        o2 += w * hav[k];
    }
    float g = sigmoidf_(o1 + o2);
    g_gate[o] = g;
    gsh[c] = g;
    __syncthreads();
    if (c < C_EMB / 2) {
        __half2 gp = __floats2half2_rn(gsh[2 * c], gsh[2 * c + 1]);
        g_gateh[(scale * NB + b) * (C_EMB / 2) + c] = *(unsigned*)&gp;
    }
}

// ---------------- fused SAM + 7x7 conv + gather: 128 thr/row, 13 nbrs/warp ----------------
__global__ void __launch_bounds__(128)
sam_gather(const int* __restrict__ idx, float* __restrict__ out,
           const float* __restrict__ sw0, const float* __restrict__ sw1,
           const float* __restrict__ sw2) {
    __shared__ float wm[98];
    __shared__ float warp_part[4];
    __shared__ float sig_sh;

    const int tid  = threadIdx.x;
    const int wid  = tid >> 5;     // 0..3
    const int lane = tid & 31;
    const int row  = blockIdx.x;
    const int b    = row / KIDX;
    const int id   = idx[row];

    const __half* Y; int HW, SIDE, scale, p;
    if (id < HW_0)              { Y = g_y0s0; HW = HW_0; SIDE = SIDE0; scale = 0; p = id; }
    else if (id < HW_0 + HW_1)  { Y = g_y0s1; HW = HW_1; SIDE = SIDE1; scale = 1; p = id - HW_0; }
    else                        { Y = g_y0s2; HW = HW_2; SIDE = SIDE2; scale = 2; p = id - (HW_0 + HW_1); }

    const float* swsrc = (scale == 0) ? sw0 : (scale == 1) ? sw1 : sw2;
    if (tid < 98) wm[tid] = swsrc[tid];
    __syncthreads();

    const int py = p / SIDE, px = p - py * SIDE;
    const __half* Yb = Y + (size_t)b * HW * C_EMB;

    uint2 gh = *(const uint2*)&g_gateh[(scale * NB + b) * (C_EMB / 2) + lane * 2];
    __half2 gl = *(__half2*)&gh.x;
    __half2 gh2 = *(__half2*)&gh.y;

    // ---- phase 1: prefetch up to 13 neighbor rows per warp (n = wid + 4*i) ----
    uint2 v[13];
    float wmaxr[13], wmeanr[13];
#pragma unroll
    for (int i = 0; i < 13; i++) {
        int n  = wid + 4 * i;
        int nn = (n < 49) ? n : 48;
        int dy = nn / 7 - 3, dx = nn - (nn / 7) * 7 - 3;
        int yy = py + dy, xx = px + dx;
        bool valid = (n < 49) && (yy >= 0) && (yy < SIDE) && (xx >= 0) && (xx < SIDE);
        wmaxr[i]  = (n < 49) ? wm[nn] : 0.0f;
        wmeanr[i] = (n < 49) ? (wm[49 + nn] * (1.0f / (float)C_EMB)) : 0.0f;
        v[i] = make_uint2(0u, 0u);
        if (valid)
            v[i] = *(const uint2*)&Yb[(size_t)(yy * SIDE + xx) * C_EMB + lane * 4];
    }

    // ---- phase 2: products + per-lane maxima + weighted mean accumulation ----
    float part = 0.0f;
    float mxv[13];
#pragma unroll
    for (int i = 0; i < 13; i++) {
        __half2 p0 = __hmul2(*(__half2*)&v[i].x, gl);
        __half2 p1 = __hmul2(*(__half2*)&v[i].y, gh2);
        float2 f0 = __half22float2(p0), f1 = __half22float2(p1);
        part += ((f0.x + f0.y) + (f1.x + f1.y)) * wmeanr[i];
        __half2 m2 = __hmax2(p0, p1);
        mxv[i] = fmaxf(__half2float(__low2half(m2)), __half2float(__high2half(m2)));
    }
    // ---- phase 3: interleaved butterfly max over all 13 values ----
#pragma unroll
    for (int o = 16; o; o >>= 1)
#pragma unroll
        for (int i = 0; i < 13; i++)
            mxv[i] = fmaxf(mxv[i], __shfl_xor_sync(0xFFFFFFFFu, mxv[i], o));
    if (lane == 0) {
#pragma unroll
        for (int i = 0; i < 13; i++) part += mxv[i] * wmaxr[i];
    }
#pragma unroll
    for (int o = 16; o; o >>= 1) part += __shfl_xor_sync(0xFFFFFFFFu, part, o);
    if (lane == 0) warp_part[wid] = part;
    __syncthreads();

    if (wid == 0) {
        float s = (lane < 4) ? warp_part[lane] : 0.0f;
#pragma unroll
        for (int o = 2; o; o >>= 1) s += __shfl_xor_sync(0xFFFFFFFFu, s, o);
        if (lane == 0) sig_sh = sigmoidf_(s);
    }
    __syncthreads();

    {
        float sig = sig_sh;
        float y = __half2float(Yb[(size_t)p * C_EMB + tid]);
        float g = g_gate[(scale * NB + b) * C_EMB + tid];
        out[(size_t)row * C_EMB + tid] = y * (1.0f + g * sig);
    }
}

// ---------------- launch ----------------
extern "C" void kernel_launch(void* const* d_in, const int* in_sizes, int n_in,
                              void* d_out, int out_size) {
    const float* x0   = (const float*)d_in[0];
    const float* x1   = (const float*)d_in[1];
    const float* x2   = (const float*)d_in[2];
    const float* yolo = (const float*)d_in[3];
    const int*   ridx = (const int*)d_in[4];
    const float* nw0 = (const float*)d_in[5];
    const float* nb0 = (const float*)d_in[6];
    const float* nw1 = (const float*)d_in[7];
    const float* nb1 = (const float*)d_in[8];
    const float* nw2 = (const float*)d_in[9];
    const float* nb2 = (const float*)d_in[10];
    const float* cw1[3] = {(const float*)d_in[11], (const float*)d_in[16], (const float*)d_in[21]};
    const float* cb1[3] = {(const float*)d_in[12], (const float*)d_in[17], (const float*)d_in[22]};
    const float* cw2[3] = {(const float*)d_in[13], (const float*)d_in[18], (const float*)d_in[23]};
    const float* cb2[3] = {(const float*)d_in[14], (const float*)d_in[19], (const float*)d_in[24]};
    const float* csw[3] = {(const float*)d_in[15], (const float*)d_in[20], (const float*)d_in[25]};

    float* out = (float*)d_out;
    const int yolo_n = NB * 8400 * 6;
    const int emb_n  = NB * KIDX * C_EMB;
    float* emb_out = out;
    if (out_size >= yolo_n + emb_n) {
        cudaMemcpyAsync(out, yolo, (size_t)in_sizes[3] * sizeof(float),
                        cudaMemcpyDeviceToDevice, 0);
        emb_out = out + yolo_n;
    }

    __half *y0p, *y1p, *y2p;
    cudaGetSymbolAddress((void**)&y0p, g_y0s0);
    cudaGetSymbolAddress((void**)&y1p, g_y0s1);
    cudaGetSymbolAddress((void**)&y2p, g_y0s2);
    __half *wh0, *wh1, *wh2;
    cudaGetSymbolAddress((void**)&wh0, g_wh0);
    cudaGetSymbolAddress((void**)&wh1, g_wh1);
    cudaGetSymbolAddress((void**)&wh2, g_wh2);

    cudaFuncSetAttribute((const void*)gemm_all,
                         cudaFuncAttributeMaxDynamicSharedMemorySize, SMEM_GEMM);

    setup_all<<<((NW0 + NW1 + NW2) / 2 + 255) / 256, 256>>>(nw0, nw1, nw2);

    gemm_all<<<dim3(132, NB), 256, SMEM_GEMM>>>(
        x0, x1, x2, wh0, wh1, wh2, nb0, nb1, nb2, y0p, y1p, y2p);

    gate_all<<<96, 128>>>(cw1[0], cb1[0], cw2[0], cb2[0],
                          cw1[1], cb1[1], cw2[1], cb2[1],
                          cw1[2], cb1[2], cw2[2], cb2[2]);

    sam_gather<<<NB * KIDX, 128>>>(ridx, emb_out, csw[0], csw[1], csw[2]);
}